// round 1
// baseline (speedup 1.0000x reference)
#include <cuda_runtime.h>
#include <math.h>

#define LEN   2048
#define BATCH 64
#define KDIM  256
#define VDIM  256
#define NH    8

// ---------------- scratch (device globals; no allocation) ----------------
__device__ float g_qpart[8 * BATCH * 2048];   // 4 MB  k-split partials of q
__device__ float g_q[BATCH * 2048];           // 512 KB q[b][h*K+k]
__device__ float g_scores[BATCH * NH * LEN];  // 4 MB  scores[b*8+h][l]
__device__ float g_m[BATCH * NH];
__device__ float g_is[BATCH * NH];
__device__ float g_rpart[16 * BATCH * 2048];  // 8 MB  l-chunk partials of read
__device__ float g_opart[16 * BATCH * VDIM];  // 1 MB  k-chunk partials of out

// ---------------- K1a: q partial GEMM: C[64,2048]=query[64,256]@Wq --------
// grid (16 j-tiles of 128, 8 k-chunks of 32), 256 thr
__global__ void __launch_bounds__(256) k_qgemm(const float* __restrict__ query,
                                               const float* __restrict__ Wq) {
    __shared__ float qy_s[64 * 32];
    int jt = blockIdx.x, kc = blockIdx.y;
    int tid = threadIdx.x;
    for (int i = tid; i < 2048; i += 256)
        qy_s[i] = query[(i >> 5) * 256 + kc * 32 + (i & 31)];
    __syncthreads();
    int j = jt * 128 + (tid & 127);
    int bbase = (tid >> 7) * 32;
    float acc[32];
#pragma unroll
    for (int i = 0; i < 32; i++) acc[i] = 0.f;
    const float4* qy4 = (const float4*)qy_s;
#pragma unroll
    for (int kk4 = 0; kk4 < 8; kk4++) {
        int krow = kc * 32 + kk4 * 4;
        float w0 = Wq[(size_t)(krow + 0) * 2048 + j];
        float w1 = Wq[(size_t)(krow + 1) * 2048 + j];
        float w2 = Wq[(size_t)(krow + 2) * 2048 + j];
        float w3 = Wq[(size_t)(krow + 3) * 2048 + j];
#pragma unroll
        for (int i = 0; i < 32; i++) {
            float4 qv = qy4[(bbase + i) * 8 + kk4];
            acc[i] += qv.x * w0 + qv.y * w1 + qv.z * w2 + qv.w * w3;
        }
    }
#pragma unroll
    for (int i = 0; i < 32; i++)
        g_qpart[(size_t)(kc * 64 + bbase + i) * 2048 + j] = acc[i];
}

// ---------------- K1b: reduce k-chunks + bias -----------------------------
__global__ void __launch_bounds__(256) k_qreduce(const float* __restrict__ bq) {
    int idx = blockIdx.x * 256 + threadIdx.x;   // idx = b*2048 + j
    int j = idx & 2047;
    float s = bq[j];
#pragma unroll
    for (int c = 0; c < 8; c++) s += g_qpart[(size_t)c * 131072 + idx];
    g_q[idx] = s;
}

// ---------------- K2: scores[l,b,h] = rpe[l,b] * <keys[l,b,:], q[b,h,:]> --
// grid (32 l-chunks of 64, 64 b), 256 thr = 8 warps (one l per warp-pass)
// lane = hg*8 + kl : hg in [0,4) covers head pair {2hg,2hg+1}, kl covers K/8
__global__ void __launch_bounds__(256) k_scores(const float* __restrict__ keys,
                                                const float* __restrict__ rpe,
                                                const int* __restrict__ steps) {
    int b = blockIdx.y;
    int lbase = blockIdx.x * 64;
    int n = steps[b];
    if (lbase >= n) return;               // dead chunk: skip HBM entirely
    int nv = n - lbase; if (nv > 64) nv = 64;

    __shared__ float q_s[2048];
    int tid = threadIdx.x;
    for (int i = tid; i < 2048; i += 256) q_s[i] = g_q[b * 2048 + i];
    __syncthreads();

    int w = tid >> 5, lane = tid & 31;
    int hg = lane >> 3, kl = lane & 7;
    int h0 = hg * 2;
    const float4* qa = ((const float4*)q_s) + h0 * 64 + kl;

    for (int lloc = w; lloc < nv; lloc += 8) {
        int l = lbase + lloc;
        const float4* kp = (const float4*)(keys + ((size_t)l * 64 + b) * 256) + kl;
        float a0 = 0.f, a1 = 0.f;
#pragma unroll
        for (int jj = 0; jj < 8; jj++) {
            float4 kv = kp[8 * jj];
            float4 q0 = qa[8 * jj];
            float4 q1 = qa[64 + 8 * jj];
            a0 += kv.x * q0.x + kv.y * q0.y + kv.z * q0.z + kv.w * q0.w;
            a1 += kv.x * q1.x + kv.y * q1.y + kv.z * q1.z + kv.w * q1.w;
        }
#pragma unroll
        for (int o = 1; o < 8; o <<= 1) {
            a0 += __shfl_xor_sync(0xffffffffu, a0, o);
            a1 += __shfl_xor_sync(0xffffffffu, a1, o);
        }
        float r = rpe[l * 64 + b];
        if (kl == 0) g_scores[(size_t)(b * 8 + h0) * 2048 + l]     = a0 * r;
        if (kl == 1) g_scores[(size_t)(b * 8 + h0 + 1) * 2048 + l] = a1 * r;
    }
}

// ---------------- K3: masked softmax stats per (b,h) ----------------------
__global__ void __launch_bounds__(256) k_softmax_stats(const int* __restrict__ steps) {
    int bh = blockIdx.x;
    int b = bh >> 3;
    int n = steps[b];
    const float* sc = g_scores + (size_t)bh * 2048;
    int tid = threadIdx.x;
    __shared__ float red[8];

    float m = -INFINITY;
    for (int l = tid; l < n; l += 256) m = fmaxf(m, sc[l]);
#pragma unroll
    for (int o = 16; o > 0; o >>= 1) m = fmaxf(m, __shfl_xor_sync(0xffffffffu, m, o));
    if ((tid & 31) == 0) red[tid >> 5] = m;
    __syncthreads();
    m = red[0];
#pragma unroll
    for (int i = 1; i < 8; i++) m = fmaxf(m, red[i]);

    float s = 0.f;
    for (int l = tid; l < n; l += 256) s += __expf(sc[l] - m);
#pragma unroll
    for (int o = 16; o > 0; o >>= 1) s += __shfl_xor_sync(0xffffffffu, s, o);
    __syncthreads();
    if ((tid & 31) == 0) red[tid >> 5] = s;
    __syncthreads();
    if (tid == 0) {
        s = 0.f;
#pragma unroll
        for (int i = 0; i < 8; i++) s += red[i];
        g_m[bh] = m;
        g_is[bh] = 1.f / s;
    }
}

// ---------------- K4: read partials: Σ_l w[l,b,h]*vals[l,b,v] -------------
// grid (16 l-chunks of 128, 64 b), 256 thr (thread = v)
__global__ void __launch_bounds__(256) k_read(const float* __restrict__ vals,
                                              const int* __restrict__ steps) {
    int c = blockIdx.x, b = blockIdx.y;
    int lbase = c * 128;
    int n = steps[b];
    int nv = n - lbase;
    if (nv > 128) nv = 128;

    __shared__ float w_s[64];
    __shared__ float m_s[8], is_s[8];
    int tid = threadIdx.x;
    if (tid < 8) { m_s[tid] = g_m[b * 8 + tid]; is_s[tid] = g_is[b * 8 + tid]; }
    __syncthreads();

    float acc[8];
#pragma unroll
    for (int h = 0; h < 8; h++) acc[h] = 0.f;

    int ng = nv > 0 ? (nv + 7) >> 3 : 0;
    for (int g = 0; g < ng; g++) {
        if (tid < 64) {                               // stage 8l x 8h weights
            int lo = tid >> 3, h = tid & 7;
            int lloc = g * 8 + lo;
            float wv = 0.f;
            if (lloc < nv)
                wv = __expf(g_scores[(size_t)(b * 8 + h) * 2048 + lbase + lloc] - m_s[h]) * is_s[h];
            w_s[lo * 8 + h] = wv;
        }
        __syncthreads();
        const float* vp = vals + ((size_t)(lbase + g * 8) * 64 + b) * 256 + tid;
        const float4* w4 = (const float4*)w_s;
#pragma unroll
        for (int lo = 0; lo < 8; lo++) {
            float v = vp[(size_t)lo * 16384];
            float4 w0 = w4[lo * 2], w1 = w4[lo * 2 + 1];
            acc[0] += w0.x * v; acc[1] += w0.y * v; acc[2] += w0.z * v; acc[3] += w0.w * v;
            acc[4] += w1.x * v; acc[5] += w1.y * v; acc[6] += w1.z * v; acc[7] += w1.w * v;
        }
        __syncthreads();
    }
#pragma unroll
    for (int h = 0; h < 8; h++)
        g_rpart[((size_t)c * 64 + b) * 2048 + h * 256 + tid] = acc[h];
}

// ---------------- K5: out partial GEMM: read[64,2048]@Wa[2048,256] --------
// grid (16 hv-chunks of 128, 8 b-tiles of 8), 256 thr (thread = vo)
__global__ void __launch_bounds__(256) k_outgemm(const float* __restrict__ Wa) {
    int kc = blockIdx.x, bt = blockIdx.y;
    __shared__ float R_s[128 * 8];   // [k][bi]
    int tid = threadIdx.x;
    for (int i = tid; i < 1024; i += 256) {
        int bi = i >> 7, k = i & 127;
        float s = 0.f;
#pragma unroll
        for (int c = 0; c < 16; c++)
            s += g_rpart[((size_t)c * 64 + bt * 8 + bi) * 2048 + kc * 128 + k];
        R_s[k * 8 + bi] = s;
    }
    __syncthreads();
    float acc[8];
#pragma unroll
    for (int i = 0; i < 8; i++) acc[i] = 0.f;
    const float4* R4 = (const float4*)R_s;
    for (int k = 0; k < 128; k++) {
        float wa = Wa[(size_t)(kc * 128 + k) * 256 + tid];
        float4 r0 = R4[k * 2], r1 = R4[k * 2 + 1];
        acc[0] += r0.x * wa; acc[1] += r0.y * wa; acc[2] += r0.z * wa; acc[3] += r0.w * wa;
        acc[4] += r1.x * wa; acc[5] += r1.y * wa; acc[6] += r1.z * wa; acc[7] += r1.w * wa;
    }
#pragma unroll
    for (int bi = 0; bi < 8; bi++)
        g_opart[((size_t)kc * 64 + bt * 8 + bi) * 256 + tid] = acc[bi];
}

// ---------------- K6: final reduce + bias ---------------------------------
__global__ void __launch_bounds__(256) k_final(const float* __restrict__ ba,
                                               float* __restrict__ out) {
    int b = blockIdx.x, vo = threadIdx.x;
    float s = ba[vo];
#pragma unroll
    for (int c = 0; c < 16; c++) s += g_opart[((size_t)c * 64 + b) * 256 + vo];
    out[b * 256 + vo] = s;
}

// ---------------- launch --------------------------------------------------
extern "C" void kernel_launch(void* const* d_in, const int* in_sizes, int n_in,
                              void* d_out, int out_size) {
    const float* query = (const float*)d_in[0];
    const float* keys  = (const float*)d_in[1];
    const float* vals  = (const float*)d_in[2];
    const float* rpe   = (const float*)d_in[3];
    const float* Wq    = (const float*)d_in[4];
    const float* bq    = (const float*)d_in[5];
    const float* Wa    = (const float*)d_in[6];
    const float* ba    = (const float*)d_in[7];
    const int*   steps = (const int*)d_in[8];
    float* out = (float*)d_out;

    k_qgemm<<<dim3(16, 8), 256>>>(query, Wq);
    k_qreduce<<<512, 256>>>(bq);
    k_scores<<<dim3(32, 64), 256>>>(keys, rpe, steps);
    k_softmax_stats<<<512, 256>>>(steps);
    k_read<<<dim3(16, 64), 256>>>(vals, steps);
    k_outgemm<<<dim3(16, 8), 256>>>(Wa);
    k_final<<<64, 256>>>(ba, out);
}